// round 1
// baseline (speedup 1.0000x reference)
#include <cuda_runtime.h>
#include <cuda_bf16.h>
#include <cstdint>

// Problem constants
#define BB 8
#define NN 1024
#define CC 768
#define HH 12
#define DD 64
#define M_ROWS (BB * NN)        // 8192
#define QKV_COLS (3 * CC)       // 2304
#define ATT_SCALE 0.125f        // 1/sqrt(64)

// Scratch (device globals: allocation-free)
__device__ float g_qkv[(size_t)M_ROWS * QKV_COLS];   // [8192, 2304]
__device__ float g_att[(size_t)M_ROWS * CC];         // [8192, 768] attention out in [B,N,C]

// ---------------------------------------------------------------------------
// Tiled SGEMM:  C[M,Ncols] = A[M,K] @ B[K,Ncols] + bias[Ncols]
// 128x128 tile, K-tile 8, 256 threads, 8x8 micro-tile per thread.
// Requires: M % 128 == 0, Ncols % 128 == 0, K % 8 == 0 (all true here).
// ---------------------------------------------------------------------------
__global__ __launch_bounds__(256) void sgemm_bias_kernel(
    const float* __restrict__ A, const float* __restrict__ B,
    const float* __restrict__ bias, float* __restrict__ C,
    int M, int Kdim, int Ncols)
{
    __shared__ float As[8][128];
    __shared__ float Bs[8][128];

    const int tid = threadIdx.x;
    const int rowBase = blockIdx.y * 128;
    const int colBase = blockIdx.x * 128;

    // A-tile load mapping: 128 rows x 8 cols, float4 per thread x1
    const int arow = tid >> 1;          // 0..127
    const int acol = (tid & 1) * 4;     // 0 or 4
    // B-tile load mapping: 8 rows x 128 cols, float4 per thread x1
    const int brow = tid >> 5;          // 0..7
    const int bcol = (tid & 31) * 4;    // 0..124

    const int ty = (tid >> 4) * 8;      // row offset of micro-tile
    const int tx = (tid & 15) * 8;      // col offset of micro-tile

    float acc[8][8];
    #pragma unroll
    for (int i = 0; i < 8; i++)
        #pragma unroll
        for (int j = 0; j < 8; j++) acc[i][j] = 0.f;

    const float* Aptr = A + (size_t)(rowBase + arow) * Kdim + acol;
    const float* Bptr = B + (size_t)brow * Ncols + colBase + bcol;

    for (int k0 = 0; k0 < Kdim; k0 += 8) {
        float4 av = *(const float4*)Aptr;
        float4 bv = *(const float4*)Bptr;
        As[acol + 0][arow] = av.x;
        As[acol + 1][arow] = av.y;
        As[acol + 2][arow] = av.z;
        As[acol + 3][arow] = av.w;
        *(float4*)&Bs[brow][bcol] = bv;
        __syncthreads();

        #pragma unroll
        for (int k = 0; k < 8; k++) {
            float a[8], bb[8];
            #pragma unroll
            for (int i = 0; i < 8; i++) a[i] = As[k][ty + i];
            #pragma unroll
            for (int j = 0; j < 8; j++) bb[j] = Bs[k][tx + j];
            #pragma unroll
            for (int i = 0; i < 8; i++)
                #pragma unroll
                for (int j = 0; j < 8; j++) acc[i][j] += a[i] * bb[j];
        }
        __syncthreads();
        Aptr += 8;
        Bptr += (size_t)8 * Ncols;
    }

    #pragma unroll
    for (int i = 0; i < 8; i++) {
        const size_t r = (size_t)(rowBase + ty + i);
        #pragma unroll
        for (int j = 0; j < 8; j += 4) {
            const int c = colBase + tx + j;
            float4 v;
            v.x = acc[i][j + 0] + bias[c + 0];
            v.y = acc[i][j + 1] + bias[c + 1];
            v.z = acc[i][j + 2] + bias[c + 2];
            v.w = acc[i][j + 3] + bias[c + 3];
            *(float4*)&C[r * Ncols + c] = v;
        }
    }
}

// ---------------------------------------------------------------------------
// Flash-style attention per (b,h): one query row per thread, online softmax.
// grid: (B*H, N/128), block: 128 threads. K/V tiles of 16 keys in smem.
// Reads Q/K/V directly from the contiguous qkv buffer [8192, 2304].
// Writes out in [B, N, C] layout (= [8192, 768]) for the projection GEMM.
// ---------------------------------------------------------------------------
#define KT 16

__global__ __launch_bounds__(128) void attn_kernel(
    const float* __restrict__ qkv, const float* __restrict__ mask,
    float* __restrict__ out)
{
    __shared__ float4 Ks[KT * 16];   // 16 keys x 64 floats
    __shared__ float4 Vs[KT * 16];

    const int bh = blockIdx.x;
    const int b = bh / HH;
    const int h = bh % HH;
    const int t = threadIdx.x;
    const int n = blockIdx.y * 128 + t;

    const size_t qrow = (size_t)(b * NN + n) * QKV_COLS + h * DD;
    float4 qv[16];
    #pragma unroll
    for (int i = 0; i < 16; i++) qv[i] = ((const float4*)(qkv + qrow))[i];

    float4 o[16];
    #pragma unroll
    for (int i = 0; i < 16; i++) o[i] = make_float4(0.f, 0.f, 0.f, 0.f);

    float mrun = -1e30f;
    float lsum = 0.f;

    const float* mrow = mask + b * NN;

    for (int m0 = 0; m0 < NN; m0 += KT) {
        __syncthreads();   // previous tile fully consumed
        // Load 16 keys x 16 float4 (K and V): 256 float4 each / 128 thr = 2 each
        #pragma unroll
        for (int i = 0; i < 2; i++) {
            const int j = t + i * 128;          // 0..255
            const int key = j >> 4;             // 0..15
            const int d4 = j & 15;              // 0..15
            const size_t base = (size_t)(b * NN + m0 + key) * QKV_COLS + h * DD + d4 * 4;
            Ks[j] = *(const float4*)(qkv + base + CC);
            Vs[j] = *(const float4*)(qkv + base + 2 * CC);
        }
        __syncthreads();

        float s[KT];
        #pragma unroll
        for (int j = 0; j < KT; j++) {
            const float4* kp = &Ks[j * 16];
            float acc = 0.f;
            #pragma unroll
            for (int kk = 0; kk < 16; kk++) {
                float4 kv = kp[kk];
                acc += qv[kk].x * kv.x + qv[kk].y * kv.y +
                       qv[kk].z * kv.z + qv[kk].w * kv.w;
            }
            s[j] = acc * ATT_SCALE + mrow[m0 + j];
        }

        float tmax = s[0];
        #pragma unroll
        for (int j = 1; j < KT; j++) tmax = fmaxf(tmax, s[j]);
        const float newm = fmaxf(mrun, tmax);
        const float corr = __expf(mrun - newm);
        lsum *= corr;
        #pragma unroll
        for (int i = 0; i < 16; i++) {
            o[i].x *= corr; o[i].y *= corr; o[i].z *= corr; o[i].w *= corr;
        }
        #pragma unroll
        for (int j = 0; j < KT; j++) {
            const float p = __expf(s[j] - newm);
            lsum += p;
            const float4* vp = &Vs[j * 16];
            #pragma unroll
            for (int kk = 0; kk < 16; kk++) {
                float4 vv = vp[kk];
                o[kk].x += p * vv.x;
                o[kk].y += p * vv.y;
                o[kk].z += p * vv.z;
                o[kk].w += p * vv.w;
            }
        }
        mrun = newm;
    }

    const float inv = 1.f / lsum;
    float* op = out + (size_t)(b * NN + n) * CC + h * DD;
    #pragma unroll
    for (int i = 0; i < 16; i++) {
        float4 v = o[i];
        v.x *= inv; v.y *= inv; v.z *= inv; v.w *= inv;
        ((float4*)op)[i] = v;
    }
}

// ---------------------------------------------------------------------------
// Launch
// ---------------------------------------------------------------------------
extern "C" void kernel_launch(void* const* d_in, const int* in_sizes, int n_in,
                              void* d_out, int out_size)
{
    const float* x      = (const float*)d_in[0];   // [8, 1024, 768]
    const float* amask  = (const float*)d_in[1];   // [8, 1, 1, 1024]
    const float* W_qkv  = (const float*)d_in[2];   // [768, 2304]
    const float* b_qkv  = (const float*)d_in[3];   // [2304]
    const float* W_proj = (const float*)d_in[4];   // [768, 768]
    const float* b_proj = (const float*)d_in[5];   // [768]
    float* out = (float*)d_out;                    // [8, 1024, 768]

    float* qkv_buf; cudaGetSymbolAddress((void**)&qkv_buf, g_qkv);
    float* att_buf; cudaGetSymbolAddress((void**)&att_buf, g_att);

    // 1) QKV projection: [8192,768] @ [768,2304] + bias
    {
        dim3 grid(QKV_COLS / 128, M_ROWS / 128);
        sgemm_bias_kernel<<<grid, 256>>>(x, W_qkv, b_qkv, qkv_buf,
                                         M_ROWS, CC, QKV_COLS);
    }
    // 2) Attention per (b,h)
    {
        dim3 grid(BB * HH, NN / 128);
        attn_kernel<<<grid, 128>>>(qkv_buf, amask, att_buf);
    }
    // 3) Output projection: [8192,768] @ [768,768] + bias -> d_out
    {
        dim3 grid(CC / 128, M_ROWS / 128);
        sgemm_bias_kernel<<<grid, 256>>>(att_buf, W_proj, b_proj, out,
                                         M_ROWS, CC, CC);
    }
}

// round 2
// speedup vs baseline: 3.1394x; 3.1394x over previous
#include <cuda_runtime.h>
#include <cuda_bf16.h>
#include <cstdint>

// Problem constants
#define BB 8
#define NN 1024
#define CC 768
#define HH 12
#define DD 64
#define M_ROWS (BB * NN)        // 8192
#define QKV_COLS (3 * CC)       // 2304
#define ATT_SCALE 0.125f        // 1/sqrt(64)

// Scratch (device globals: allocation-free)
__device__ float g_qkv[(size_t)M_ROWS * QKV_COLS];   // [8192, 2304]
__device__ float g_att[(size_t)M_ROWS * CC];         // [8192, 768]

// ---------------------------------------------------------------------------
// helpers
// ---------------------------------------------------------------------------
__device__ __forceinline__ unsigned f2tf(float f) {
    unsigned r;
    asm("cvt.rna.tf32.f32 %0, %1;" : "=r"(r) : "f"(f));
    return r;
}

__device__ __forceinline__ void mma_tf32(float c[4], const unsigned a[4], const unsigned b[2]) {
    asm volatile(
        "mma.sync.aligned.m16n8k8.row.col.f32.tf32.tf32.f32 "
        "{%0,%1,%2,%3},{%4,%5,%6,%7},{%8,%9},{%0,%1,%2,%3};"
        : "+f"(c[0]), "+f"(c[1]), "+f"(c[2]), "+f"(c[3])
        : "r"(a[0]), "r"(a[1]), "r"(a[2]), "r"(a[3]), "r"(b[0]), "r"(b[1]));
}

// ---------------------------------------------------------------------------
// TF32 tensor-core GEMM:  C[M,Ncols] = A[M,K] @ B[K,Ncols] + bias
// 128x128 tile, BK=16, 256 threads (8 warps, 4x2), warp tile 32x64.
// Conflict-free fragment smem layouts: As[m][k] stride 20, Bs[k][n] stride 136.
// ---------------------------------------------------------------------------
#define ASTR 20
#define BSTR 136

__global__ __launch_bounds__(256) void gemm_tf32_kernel(
    const float* __restrict__ A, const float* __restrict__ B,
    const float* __restrict__ bias, float* __restrict__ C,
    int M, int Kdim, int Ncols)
{
    __shared__ unsigned As[128 * ASTR];
    __shared__ unsigned Bs[16 * BSTR];

    const int tid  = threadIdx.x;
    const int lane = tid & 31;
    const int wid  = tid >> 5;
    const int wm   = wid >> 1;          // 0..3 -> m offset wm*32
    const int wn   = wid & 1;           // 0..1 -> n offset wn*64
    const int r    = lane >> 2;         // 0..7
    const int q    = lane & 3;          // 0..3

    const int rowBase = blockIdx.y * 128;
    const int colBase = blockIdx.x * 128;

    // A staging map: row = tid>>1 (0..127), kc = (tid&1)*8
    const int arow = tid >> 1;
    const int akc  = (tid & 1) * 8;
    // B staging map: row = tid>>4 (0..15), col = (tid&15)*8
    const int brow = tid >> 4;
    const int bcol = (tid & 15) * 8;

    const float* Ap = A + (size_t)(rowBase + arow) * Kdim + akc;
    const float* Bp = B + (size_t)brow * Ncols + colBase + bcol;

    float acc[2][8][4];
    #pragma unroll
    for (int mf = 0; mf < 2; mf++)
        #pragma unroll
        for (int nf = 0; nf < 8; nf++)
            #pragma unroll
            for (int c = 0; c < 4; c++) acc[mf][nf][c] = 0.f;

    float4 aReg0 = ((const float4*)Ap)[0];
    float4 aReg1 = ((const float4*)Ap)[1];
    float4 bReg0 = ((const float4*)Bp)[0];
    float4 bReg1 = ((const float4*)Bp)[1];

    for (int k0 = 0; k0 < Kdim; k0 += 16) {
        // store staged regs -> smem (convert to tf32)
        {
            uint4 u0 = make_uint4(f2tf(aReg0.x), f2tf(aReg0.y), f2tf(aReg0.z), f2tf(aReg0.w));
            uint4 u1 = make_uint4(f2tf(aReg1.x), f2tf(aReg1.y), f2tf(aReg1.z), f2tf(aReg1.w));
            *(uint4*)&As[arow * ASTR + akc]     = u0;
            *(uint4*)&As[arow * ASTR + akc + 4] = u1;
            uint4 v0 = make_uint4(f2tf(bReg0.x), f2tf(bReg0.y), f2tf(bReg0.z), f2tf(bReg0.w));
            uint4 v1 = make_uint4(f2tf(bReg1.x), f2tf(bReg1.y), f2tf(bReg1.z), f2tf(bReg1.w));
            *(uint4*)&Bs[brow * BSTR + bcol]     = v0;
            *(uint4*)&Bs[brow * BSTR + bcol + 4] = v1;
        }
        __syncthreads();

        // prefetch next tile
        if (k0 + 16 < Kdim) {
            const float* Apn = Ap + 16;
            const float* Bpn = Bp + (size_t)16 * Ncols;
            aReg0 = ((const float4*)Apn)[0];
            aReg1 = ((const float4*)Apn)[1];
            bReg0 = ((const float4*)Bpn)[0];
            bReg1 = ((const float4*)Bpn)[1];
            Ap = Apn;
            Bp = Bpn;
        }

        // compute: 2 k-steps of 8
        #pragma unroll
        for (int ks = 0; ks < 2; ks++) {
            const int kb = ks * 8;
            unsigned af[2][4];
            #pragma unroll
            for (int mf = 0; mf < 2; mf++) {
                const int mb = wm * 32 + mf * 16;
                af[mf][0] = As[(mb + r) * ASTR + kb + q];
                af[mf][1] = As[(mb + 8 + r) * ASTR + kb + q];
                af[mf][2] = As[(mb + r) * ASTR + kb + 4 + q];
                af[mf][3] = As[(mb + 8 + r) * ASTR + kb + 4 + q];
            }
            unsigned bf[8][2];
            #pragma unroll
            for (int nf = 0; nf < 8; nf++) {
                const int nb = wn * 64 + nf * 8;
                bf[nf][0] = Bs[(kb + q) * BSTR + nb + r];
                bf[nf][1] = Bs[(kb + 4 + q) * BSTR + nb + r];
            }
            #pragma unroll
            for (int mf = 0; mf < 2; mf++)
                #pragma unroll
                for (int nf = 0; nf < 8; nf++)
                    mma_tf32(acc[mf][nf], af[mf], bf[nf]);
        }
        __syncthreads();
    }

    // epilogue: bias + store
    #pragma unroll
    for (int mf = 0; mf < 2; mf++) {
        const int row0 = rowBase + wm * 32 + mf * 16 + r;
        #pragma unroll
        for (int nf = 0; nf < 8; nf++) {
            const int col = colBase + wn * 64 + nf * 8 + 2 * q;
            const float2 bv = *(const float2*)&bias[col];
            float2 v0, v1;
            v0.x = acc[mf][nf][0] + bv.x;
            v0.y = acc[mf][nf][1] + bv.y;
            v1.x = acc[mf][nf][2] + bv.x;
            v1.y = acc[mf][nf][3] + bv.y;
            *(float2*)&C[(size_t)row0 * Ncols + col]       = v0;
            *(float2*)&C[(size_t)(row0 + 8) * Ncols + col] = v1;
        }
    }
}

// ---------------------------------------------------------------------------
// Flash attention with TF32 tensor cores.
// CTA = (b, h, 64-row Q tile). 4 warps x 16 Q rows. K/V tiles of 64 keys.
// smem: Qs[64][68] (reused per-warp as P buffer), Ks[64][72] ([d][key],
// XOR-swizzled), Vs[64][72] ([key][d]), Ms[1024] (mask row).
// ---------------------------------------------------------------------------
#define QSTR 68
#define KSTR 72
#define SM_Q 0
#define SM_K (64 * QSTR)               // 4352
#define SM_V (SM_K + 64 * KSTR)       // 8960
#define SM_M (SM_V + 64 * KSTR)       // 13568
#define SM_TOTAL_F (SM_M + 1024)      // 14592 floats = 58368 B

#define KS_IDX(d, key) ((d) * KSTR + ((key) ^ (((d) >> 2) & 7)))

__global__ __launch_bounds__(128) void attn_tf32_kernel(
    const float* __restrict__ qkv, const float* __restrict__ mask,
    float* __restrict__ out)
{
    extern __shared__ float smf[];
    unsigned* smu = (unsigned*)smf;

    const int bh = blockIdx.x;
    const int b  = bh / HH;
    const int h  = bh % HH;
    const int qt = blockIdx.y;         // q tile (64 rows)

    const int tid  = threadIdx.x;
    const int lane = tid & 31;
    const int w    = tid >> 5;
    const int r    = lane >> 2;
    const int q    = lane & 3;

    // ---- stage mask row ----
    #pragma unroll
    for (int i = 0; i < 2; i++) {
        const int j = tid + i * 128;
        ((float4*)&smf[SM_M])[j] = ((const float4*)(mask + b * NN))[j];
    }
    // ---- stage Q tile [64][64] -> Qs (tf32) ----
    #pragma unroll
    for (int i = 0; i < 8; i++) {
        const int j   = i * 128 + tid;
        const int row = j >> 4;
        const int c4  = j & 15;
        const float4 v = *(const float4*)(qkv +
            (size_t)(b * NN + qt * 64 + row) * QKV_COLS + h * DD + c4 * 4);
        *(uint4*)&smu[SM_Q + row * QSTR + c4 * 4] =
            make_uint4(f2tf(v.x), f2tf(v.y), f2tf(v.z), f2tf(v.w));
    }
    __syncthreads();

    // ---- Q fragments (persistent in regs): 8 k-steps x 4 ----
    unsigned qf[8][4];
    {
        const int rb = w * 16;
        #pragma unroll
        for (int ks = 0; ks < 8; ks++) {
            const int kb = ks * 8;
            qf[ks][0] = smu[SM_Q + (rb + r) * QSTR + kb + q];
            qf[ks][1] = smu[SM_Q + (rb + 8 + r) * QSTR + kb + q];
            qf[ks][2] = smu[SM_Q + (rb + r) * QSTR + kb + 4 + q];
            qf[ks][3] = smu[SM_Q + (rb + 8 + r) * QSTR + kb + 4 + q];
        }
    }

    // per-warp P buffer = this warp's 16 rows of Qs region
    unsigned* Pw = &smu[SM_Q + (w * 16) * QSTR];

    float o[8][4];
    #pragma unroll
    for (int nf = 0; nf < 8; nf++)
        #pragma unroll
        for (int c = 0; c < 4; c++) o[nf][c] = 0.f;
    float m0 = -1e30f, m1 = -1e30f;
    float l0 = 0.f, l1 = 0.f;

    for (int kt = 0; kt < NN / 64; kt++) {
        __syncthreads();   // previous tile fully consumed
        // ---- stage K (transposed, swizzled) and V ----
        #pragma unroll
        for (int i = 0; i < 8; i++) {
            const int j   = i * 128 + tid;
            const int key = j >> 4;
            const int c4  = j & 15;
            const size_t base = (size_t)(b * NN + kt * 64 + key) * QKV_COLS + h * DD + c4 * 4;
            const float4 kv = *(const float4*)(qkv + base + CC);
            const float4 vv = *(const float4*)(qkv + base + 2 * CC);
            const int swz = key ^ (c4 & 7);
            smu[SM_K + (c4 * 4 + 0) * KSTR + swz] = f2tf(kv.x);
            smu[SM_K + (c4 * 4 + 1) * KSTR + swz] = f2tf(kv.y);
            smu[SM_K + (c4 * 4 + 2) * KSTR + swz] = f2tf(kv.z);
            smu[SM_K + (c4 * 4 + 3) * KSTR + swz] = f2tf(kv.w);
            *(uint4*)&smu[SM_V + key * KSTR + c4 * 4] =
                make_uint4(f2tf(vv.x), f2tf(vv.y), f2tf(vv.z), f2tf(vv.w));
        }
        __syncthreads();

        // ---- S = Q K^T : warp computes 16x64 ----
        float s[8][4];
        #pragma unroll
        for (int nf = 0; nf < 8; nf++)
            #pragma unroll
            for (int c = 0; c < 4; c++) s[nf][c] = 0.f;

        #pragma unroll
        for (int ks = 0; ks < 8; ks++) {
            const int kb = ks * 8;
            #pragma unroll
            for (int nf = 0; nf < 8; nf++) {
                const int cb = nf * 8;
                unsigned bf[2];
                bf[0] = smu[SM_K + KS_IDX(kb + q,     cb + r)];
                bf[1] = smu[SM_K + KS_IDX(kb + 4 + q, cb + r)];
                mma_tf32(s[nf], qf[ks], bf);
            }
        }

        // ---- scale + mask, online softmax ----
        float tmax0 = -1e30f, tmax1 = -1e30f;
        #pragma unroll
        for (int nf = 0; nf < 8; nf++) {
            const int col = kt * 64 + nf * 8 + 2 * q;
            const float2 mv = *(const float2*)&smf[SM_M + col];
            s[nf][0] = s[nf][0] * ATT_SCALE + mv.x;
            s[nf][1] = s[nf][1] * ATT_SCALE + mv.y;
            s[nf][2] = s[nf][2] * ATT_SCALE + mv.x;
            s[nf][3] = s[nf][3] * ATT_SCALE + mv.y;
            tmax0 = fmaxf(tmax0, fmaxf(s[nf][0], s[nf][1]));
            tmax1 = fmaxf(tmax1, fmaxf(s[nf][2], s[nf][3]));
        }
        #pragma unroll
        for (int off = 1; off <= 2; off <<= 1) {
            tmax0 = fmaxf(tmax0, __shfl_xor_sync(0xffffffffu, tmax0, off));
            tmax1 = fmaxf(tmax1, __shfl_xor_sync(0xffffffffu, tmax1, off));
        }
        const float nm0 = fmaxf(m0, tmax0);
        const float nm1 = fmaxf(m1, tmax1);
        const float cr0 = __expf(m0 - nm0);
        const float cr1 = __expf(m1 - nm1);
        l0 *= cr0; l1 *= cr1;
        #pragma unroll
        for (int nf = 0; nf < 8; nf++) {
            o[nf][0] *= cr0; o[nf][1] *= cr0;
            o[nf][2] *= cr1; o[nf][3] *= cr1;
        }
        m0 = nm0; m1 = nm1;

        // p = exp(s - m), accumulate l, store to P buffer (tf32, C-frag layout)
        #pragma unroll
        for (int nf = 0; nf < 8; nf++) {
            const float p0 = __expf(s[nf][0] - nm0);
            const float p1 = __expf(s[nf][1] - nm0);
            const float p2 = __expf(s[nf][2] - nm1);
            const float p3 = __expf(s[nf][3] - nm1);
            l0 += p0 + p1;
            l1 += p2 + p3;
            const int col = nf * 8 + 2 * q;
            *(uint2*)&Pw[r * QSTR + col]       = make_uint2(f2tf(p0), f2tf(p1));
            *(uint2*)&Pw[(r + 8) * QSTR + col] = make_uint2(f2tf(p2), f2tf(p3));
        }
        __syncwarp();

        // ---- O += P V ----
        #pragma unroll
        for (int ks = 0; ks < 8; ks++) {
            const int kb = ks * 8;
            unsigned af[4];
            af[0] = Pw[r * QSTR + kb + q];
            af[1] = Pw[(r + 8) * QSTR + kb + q];
            af[2] = Pw[r * QSTR + kb + 4 + q];
            af[3] = Pw[(r + 8) * QSTR + kb + 4 + q];
            #pragma unroll
            for (int nf = 0; nf < 8; nf++) {
                const int cb = nf * 8;
                unsigned bf[2];
                bf[0] = smu[SM_V + (kb + q) * KSTR + cb + r];
                bf[1] = smu[SM_V + (kb + 4 + q) * KSTR + cb + r];
                mma_tf32(o[nf], af, bf);
            }
        }
        __syncwarp();
    }

    // ---- finalize: divide by l, store to [B,N,C] ----
    #pragma unroll
    for (int off = 1; off <= 2; off <<= 1) {
        l0 += __shfl_xor_sync(0xffffffffu, l0, off);
        l1 += __shfl_xor_sync(0xffffffffu, l1, off);
    }
    const float inv0 = 1.f / l0;
    const float inv1 = 1.f / l1;

    const int row0 = b * NN + qt * 64 + w * 16 + r;
    #pragma unroll
    for (int nf = 0; nf < 8; nf++) {
        const int col = h * DD + nf * 8 + 2 * q;
        float2 v0, v1;
        v0.x = o[nf][0] * inv0; v0.y = o[nf][1] * inv0;
        v1.x = o[nf][2] * inv1; v1.y = o[nf][3] * inv1;
        *(float2*)&out[(size_t)row0 * CC + col]       = v0;
        *(float2*)&out[(size_t)(row0 + 8) * CC + col] = v1;
    }
}

// ---------------------------------------------------------------------------
// Launch
// ---------------------------------------------------------------------------
extern "C" void kernel_launch(void* const* d_in, const int* in_sizes, int n_in,
                              void* d_out, int out_size)
{
    const float* x      = (const float*)d_in[0];
    const float* amask  = (const float*)d_in[1];
    const float* W_qkv  = (const float*)d_in[2];
    const float* b_qkv  = (const float*)d_in[3];
    const float* W_proj = (const float*)d_in[4];
    const float* b_proj = (const float*)d_in[5];
    float* out = (float*)d_out;

    float* qkv_buf; cudaGetSymbolAddress((void**)&qkv_buf, g_qkv);
    float* att_buf; cudaGetSymbolAddress((void**)&att_buf, g_att);

    static bool attr_set = false;
    if (!attr_set) {
        cudaFuncSetAttribute(attn_tf32_kernel,
                             cudaFuncAttributeMaxDynamicSharedMemorySize,
                             SM_TOTAL_F * 4);
        attr_set = true;
    }

    // 1) QKV projection
    {
        dim3 grid(QKV_COLS / 128, M_ROWS / 128);
        gemm_tf32_kernel<<<grid, 256>>>(x, W_qkv, b_qkv, qkv_buf,
                                        M_ROWS, CC, QKV_COLS);
    }
    // 2) Attention
    {
        dim3 grid(BB * HH, NN / 64);
        attn_tf32_kernel<<<grid, 128, SM_TOTAL_F * 4>>>(qkv_buf, amask, att_buf);
    }
    // 3) Output projection
    {
        dim3 grid(CC / 128, M_ROWS / 128);
        gemm_tf32_kernel<<<grid, 256>>>(att_buf, W_proj, b_proj, out,
                                        M_ROWS, CC, CC);
    }
}

// round 3
// speedup vs baseline: 8.2596x; 2.6309x over previous
#include <cuda_runtime.h>
#include <cuda_fp16.h>
#include <cstdint>

#define BB 8
#define NN 1024
#define CC 768
#define HH 12
#define DD 64
#define M_ROWS (BB * NN)        // 8192
#define QKV_COLS (3 * CC)       // 2304
#define ATT_SCALE 0.125f

// Scratch (device globals: allocation-free)
__device__ __half g_x_h[(size_t)M_ROWS * CC];
__device__ __half g_wqkv_t[(size_t)QKV_COLS * CC];   // [2304][768]
__device__ __half g_wproj_t[(size_t)CC * CC];        // [768][768]
__device__ __half g_qkv_h[(size_t)M_ROWS * QKV_COLS];
__device__ __half g_att_h[(size_t)M_ROWS * CC];

// ---------------------------------------------------------------------------
// PTX helpers
// ---------------------------------------------------------------------------
__device__ __forceinline__ unsigned sptr(const void* p) {
    return (unsigned)__cvta_generic_to_shared(p);
}
__device__ __forceinline__ void cp16(unsigned s, const void* g) {
    asm volatile("cp.async.cg.shared.global [%0], [%1], 16;\n" :: "r"(s), "l"(g));
}
__device__ __forceinline__ void cp_commit() {
    asm volatile("cp.async.commit_group;\n");
}
template <int N>
__device__ __forceinline__ void cp_wait() {
    asm volatile("cp.async.wait_group %0;\n" :: "n"(N));
}
__device__ __forceinline__ void ldsm4(unsigned r[4], unsigned a) {
    asm volatile("ldmatrix.sync.aligned.m8n8.x4.shared.b16 {%0,%1,%2,%3}, [%4];\n"
                 : "=r"(r[0]), "=r"(r[1]), "=r"(r[2]), "=r"(r[3]) : "r"(a));
}
__device__ __forceinline__ void ldsm4t(unsigned r[4], unsigned a) {
    asm volatile("ldmatrix.sync.aligned.m8n8.x4.trans.shared.b16 {%0,%1,%2,%3}, [%4];\n"
                 : "=r"(r[0]), "=r"(r[1]), "=r"(r[2]), "=r"(r[3]) : "r"(a));
}
__device__ __forceinline__ void mma16816(float c[4], const unsigned a[4],
                                         unsigned b0, unsigned b1) {
    asm volatile(
        "mma.sync.aligned.m16n8k16.row.col.f32.f16.f16.f32 "
        "{%0,%1,%2,%3},{%4,%5,%6,%7},{%8,%9},{%0,%1,%2,%3};\n"
        : "+f"(c[0]), "+f"(c[1]), "+f"(c[2]), "+f"(c[3])
        : "r"(a[0]), "r"(a[1]), "r"(a[2]), "r"(a[3]), "r"(b0), "r"(b1));
}
__device__ __forceinline__ unsigned f2h2(float lo, float hi) {
    __half2 h = __floats2half2_rn(lo, hi);
    return *(unsigned*)&h;
}
__device__ __forceinline__ void store2(__half* p, float x, float y) {
    *(__half2*)p = __floats2half2_rn(x, y);
}
__device__ __forceinline__ void store2(float* p, float x, float y) {
    *(float2*)p = make_float2(x, y);
}

// ---------------------------------------------------------------------------
// fp32 -> fp16 convert (vectorized)
// ---------------------------------------------------------------------------
__global__ void cvt_f32_f16_kernel(const float* __restrict__ in,
                                   __half* __restrict__ out, int n4) {
    int i = blockIdx.x * 256 + threadIdx.x;
    if (i < n4) {
        float4 v = ((const float4*)in)[i];
        __half2 h0 = __floats2half2_rn(v.x, v.y);
        __half2 h1 = __floats2half2_rn(v.z, v.w);
        ((uint2*)out)[i] = make_uint2(*(unsigned*)&h0, *(unsigned*)&h1);
    }
}

// ---------------------------------------------------------------------------
// transpose + convert: W[rows][cols] f32 -> Wt[cols][rows] f16
// ---------------------------------------------------------------------------
__global__ void transpose_cvt_kernel(const float* __restrict__ W,
                                     __half* __restrict__ Wt,
                                     int rows, int cols) {
    __shared__ float t[32][33];
    const int x  = blockIdx.x * 32 + threadIdx.x;
    const int y0 = blockIdx.y * 32 + threadIdx.y;
    #pragma unroll
    for (int i = 0; i < 4; i++)
        t[threadIdx.y + i * 8][threadIdx.x] = W[(size_t)(y0 + i * 8) * cols + x];
    __syncthreads();
    const int xo  = blockIdx.y * 32 + threadIdx.x;
    const int yo0 = blockIdx.x * 32 + threadIdx.y;
    #pragma unroll
    for (int i = 0; i < 4; i++)
        Wt[(size_t)(yo0 + i * 8) * rows + xo] =
            __float2half(t[threadIdx.x][threadIdx.y + i * 8]);
}

// ---------------------------------------------------------------------------
// fp16 tensor-core GEMM: C[M,N] = A[M,K] @ Bt[N,K]^T + bias
// A fp16 [M][K], Bt fp16 [N][K] (pre-transposed). 128x128x32 tiles.
// 256 threads, 8 warps (4m x 2n), warp tile 32x64. cp.async double-buffered.
// smem chunk layout: 16B chunks, 4 per row (64B rows), swizzle c ^= (row>>1)&3.
// ---------------------------------------------------------------------------
template <typename OutT>
__global__ __launch_bounds__(256) void gemm_f16_kernel(
    const __half* __restrict__ A, const __half* __restrict__ Bt,
    const float* __restrict__ bias, OutT* __restrict__ C,
    int M, int Kdim, int Ncols)
{
    __shared__ uint4 As[2][512];   // 128 rows x 4 chunks
    __shared__ uint4 Bs[2][512];

    const int tid  = threadIdx.x;
    const int lane = tid & 31;
    const int wid  = tid >> 5;
    const int wm   = wid >> 1;
    const int wn   = wid & 1;
    const int r    = lane >> 2;
    const int q    = lane & 3;
    const int mat  = lane >> 3;
    const int mi   = lane & 7;

    const int rowBase = blockIdx.y * 128;
    const int colBase = blockIdx.x * 128;

    const unsigned sA0 = sptr(&As[0][0]);
    const unsigned sB0 = sptr(&Bs[0][0]);

    float acc[2][8][4];
    #pragma unroll
    for (int mb = 0; mb < 2; mb++)
        #pragma unroll
        for (int nf = 0; nf < 8; nf++)
            #pragma unroll
            for (int c = 0; c < 4; c++) acc[mb][nf][c] = 0.f;

    const int ntiles = Kdim >> 5;

    // staging: thread stages 2 A-chunks + 2 B-chunks per tile
    const int srow = tid >> 2;          // 0..63
    const int sc0  = tid & 3;

    auto stage = [&](int buf, int k0) {
        #pragma unroll
        for (int i = 0; i < 2; i++) {
            const int row = srow + i * 64;
            const int swz = sc0 ^ ((row >> 1) & 3);
            cp16(sA0 + (buf * 512 + row * 4 + swz) * 16,
                 A + (size_t)(rowBase + row) * Kdim + k0 + sc0 * 8);
            cp16(sB0 + (buf * 512 + row * 4 + swz) * 16,
                 Bt + (size_t)(colBase + row) * Kdim + k0 + sc0 * 8);
        }
        cp_commit();
    };

    stage(0, 0);

    for (int it = 0; it < ntiles; it++) {
        if (it + 1 < ntiles) { stage((it + 1) & 1, (it + 1) * 32); cp_wait<1>(); }
        else                 { cp_wait<0>(); }
        __syncthreads();

        const unsigned sAb = sA0 + (it & 1) * 512 * 16;
        const unsigned sBb = sB0 + (it & 1) * 512 * 16;

        #pragma unroll
        for (int ks = 0; ks < 2; ks++) {
            unsigned af[2][4];
            #pragma unroll
            for (int mb = 0; mb < 2; mb++) {
                const int rowA = wm * 32 + mb * 16 + (mat & 1) * 8 + mi;
                const int ch   = 2 * ks + (mat >> 1);
                ldsm4(af[mb], sAb + (rowA * 4 + (ch ^ ((rowA >> 1) & 3))) * 16);
            }
            unsigned bf[4][4];
            #pragma unroll
            for (int np = 0; np < 4; np++) {
                const int rowB = wn * 64 + np * 16 + (mat & 1) * 8 + mi;
                const int ch   = 2 * ks + (mat >> 1);
                ldsm4(bf[np], sBb + (rowB * 4 + (ch ^ ((rowB >> 1) & 3))) * 16);
            }
            #pragma unroll
            for (int mb = 0; mb < 2; mb++)
                #pragma unroll
                for (int nf = 0; nf < 8; nf++)
                    mma16816(acc[mb][nf], af[mb],
                             bf[nf >> 1][nf & 1], bf[nf >> 1][(nf & 1) + 2]);
        }
        __syncthreads();
    }

    // epilogue
    #pragma unroll
    for (int mb = 0; mb < 2; mb++) {
        const int row0 = rowBase + wm * 32 + mb * 16 + r;
        #pragma unroll
        for (int nf = 0; nf < 8; nf++) {
            const int col = colBase + wn * 64 + nf * 8 + 2 * q;
            const float2 bv = *(const float2*)&bias[col];
            store2(&C[(size_t)row0 * Ncols + col],
                   acc[mb][nf][0] + bv.x, acc[mb][nf][1] + bv.y);
            store2(&C[(size_t)(row0 + 8) * Ncols + col],
                   acc[mb][nf][2] + bv.x, acc[mb][nf][3] + bv.y);
        }
    }
}

// ---------------------------------------------------------------------------
// fp16 flash attention. CTA = (b,h, 64 q-rows), 4 warps x 16 rows.
// K tiles of 64 keys, cp.async double-buffered. P stays in registers
// (S C-fragment layout == PV A-fragment layout).
// smem rows: 64 halves = 8 chunks of 16B, swizzle c ^= row&7.
// ---------------------------------------------------------------------------
__global__ __launch_bounds__(128) void attn_f16_kernel(
    const __half* __restrict__ qkv, const float* __restrict__ mask,
    __half* __restrict__ out)
{
    __shared__ uint4 Qs[512];            // 64 x 8 chunks
    __shared__ uint4 KVs[2][2][512];     // [stage][K/V]
    __shared__ float Ms[NN];

    const int bh = blockIdx.x;
    const int b  = bh / HH;
    const int h  = bh % HH;
    const int qt = blockIdx.y;

    const int tid  = threadIdx.x;
    const int lane = tid & 31;
    const int w    = tid >> 5;
    const int r    = lane >> 2;
    const int q    = lane & 3;
    const int mat  = lane >> 3;
    const int mi   = lane & 7;

    const unsigned sQ  = sptr(Qs);
    const unsigned sKV = sptr(&KVs[0][0][0]);

    // stage Q (group 0)
    #pragma unroll
    for (int i = 0; i < 4; i++) {
        const int j = tid + i * 128;
        const int row = j >> 3, c0 = j & 7;
        cp16(sQ + (row * 8 + (c0 ^ (row & 7))) * 16,
             qkv + (size_t)(b * NN + qt * 64 + row) * QKV_COLS + h * DD + c0 * 8);
    }
    cp_commit();

    auto stageKV = [&](int buf, int kt) {
        #pragma unroll
        for (int i = 0; i < 8; i++) {
            const int j  = tid + i * 128;           // 0..1023
            const int kv = j >> 9;                  // 0=K, 1=V
            const int jj = j & 511;
            const int row = jj >> 3, c0 = jj & 7;
            cp16(sKV + (buf * 1024 + kv * 512 + row * 8 + (c0 ^ (row & 7))) * 16,
                 qkv + (size_t)(b * NN + kt * 64 + row) * QKV_COLS +
                     (kv + 1) * CC + h * DD + c0 * 8);
        }
        cp_commit();
    };

    stageKV(0, 0);

    // stage mask (plain loads)
    #pragma unroll
    for (int i = 0; i < 2; i++) {
        const int j = tid + i * 128;
        ((float4*)Ms)[j] = ((const float4*)(mask + b * NN))[j];
    }

    cp_wait<0>();
    __syncthreads();

    // Q fragments, persistent
    unsigned qf[4][4];
    #pragma unroll
    for (int ks = 0; ks < 4; ks++) {
        const int rowQ = w * 16 + (mat & 1) * 8 + mi;
        const int ch   = 2 * ks + (mat >> 1);
        ldsm4(qf[ks], sQ + (rowQ * 8 + (ch ^ (rowQ & 7))) * 16);
    }

    float o[8][4];
    #pragma unroll
    for (int nf = 0; nf < 8; nf++)
        #pragma unroll
        for (int c = 0; c < 4; c++) o[nf][c] = 0.f;
    float m0 = -1e30f, m1 = -1e30f, l0 = 0.f, l1 = 0.f;

    for (int kt = 0; kt < NN / 64; kt++) {
        if (kt + 1 < NN / 64) { stageKV((kt + 1) & 1, kt + 1); cp_wait<1>(); }
        else                  { cp_wait<0>(); }
        __syncthreads();

        const unsigned sK = sKV + (kt & 1) * 1024 * 16;
        const unsigned sV = sK + 512 * 16;

        // ---- S = Q K^T ----
        float s[8][4];
        #pragma unroll
        for (int nf = 0; nf < 8; nf++)
            #pragma unroll
            for (int c = 0; c < 4; c++) s[nf][c] = 0.f;

        #pragma unroll
        for (int ks = 0; ks < 4; ks++) {
            unsigned bk[4][4];
            #pragma unroll
            for (int np = 0; np < 4; np++) {
                const int rowK = np * 16 + (mat & 1) * 8 + mi;
                const int ch   = 2 * ks + (mat >> 1);
                ldsm4(bk[np], sK + (rowK * 8 + (ch ^ (rowK & 7))) * 16);
            }
            #pragma unroll
            for (int nf = 0; nf < 8; nf++)
                mma16816(s[nf], qf[ks],
                         bk[nf >> 1][nf & 1], bk[nf >> 1][(nf & 1) + 2]);
        }

        // ---- scale + mask + online softmax ----
        float tmax0 = -1e30f, tmax1 = -1e30f;
        #pragma unroll
        for (int nf = 0; nf < 8; nf++) {
            const int col = kt * 64 + nf * 8 + 2 * q;
            const float2 mv = *(const float2*)&Ms[col];
            s[nf][0] = s[nf][0] * ATT_SCALE + mv.x;
            s[nf][1] = s[nf][1] * ATT_SCALE + mv.y;
            s[nf][2] = s[nf][2] * ATT_SCALE + mv.x;
            s[nf][3] = s[nf][3] * ATT_SCALE + mv.y;
            tmax0 = fmaxf(tmax0, fmaxf(s[nf][0], s[nf][1]));
            tmax1 = fmaxf(tmax1, fmaxf(s[nf][2], s[nf][3]));
        }
        #pragma unroll
        for (int off = 1; off <= 2; off <<= 1) {
            tmax0 = fmaxf(tmax0, __shfl_xor_sync(0xffffffffu, tmax0, off));
            tmax1 = fmaxf(tmax1, __shfl_xor_sync(0xffffffffu, tmax1, off));
        }
        const float nm0 = fmaxf(m0, tmax0);
        const float nm1 = fmaxf(m1, tmax1);
        const float cr0 = __expf(m0 - nm0);
        const float cr1 = __expf(m1 - nm1);
        l0 *= cr0; l1 *= cr1;
        #pragma unroll
        for (int nf = 0; nf < 8; nf++) {
            o[nf][0] *= cr0; o[nf][1] *= cr0;
            o[nf][2] *= cr1; o[nf][3] *= cr1;
        }
        m0 = nm0; m1 = nm1;

        #pragma unroll
        for (int nf = 0; nf < 8; nf++) {
            s[nf][0] = __expf(s[nf][0] - nm0);
            s[nf][1] = __expf(s[nf][1] - nm0);
            s[nf][2] = __expf(s[nf][2] - nm1);
            s[nf][3] = __expf(s[nf][3] - nm1);
            l0 += s[nf][0] + s[nf][1];
            l1 += s[nf][2] + s[nf][3];
        }

        // ---- P fragments in registers (C-frag layout == A-frag layout) ----
        unsigned ap[4][4];
        #pragma unroll
        for (int ks = 0; ks < 4; ks++) {
            ap[ks][0] = f2h2(s[2 * ks][0],     s[2 * ks][1]);
            ap[ks][1] = f2h2(s[2 * ks][2],     s[2 * ks][3]);
            ap[ks][2] = f2h2(s[2 * ks + 1][0], s[2 * ks + 1][1]);
            ap[ks][3] = f2h2(s[2 * ks + 1][2], s[2 * ks + 1][3]);
        }

        // ---- O += P V ----
        #pragma unroll
        for (int ks = 0; ks < 4; ks++) {
            unsigned bv[4][4];
            #pragma unroll
            for (int np = 0; np < 4; np++) {
                const int rowV = ks * 16 + (mat & 1) * 8 + mi;
                const int ch   = 2 * np + (mat >> 1);
                ldsm4t(bv[np], sV + (rowV * 8 + (ch ^ (rowV & 7))) * 16);
            }
            #pragma unroll
            for (int nf = 0; nf < 8; nf++)
                mma16816(o[nf], ap[ks],
                         bv[nf >> 1][(nf & 1) * 2], bv[nf >> 1][(nf & 1) * 2 + 1]);
        }
        __syncthreads();
    }

    // ---- finalize ----
    #pragma unroll
    for (int off = 1; off <= 2; off <<= 1) {
        l0 += __shfl_xor_sync(0xffffffffu, l0, off);
        l1 += __shfl_xor_sync(0xffffffffu, l1, off);
    }
    const float inv0 = 1.f / l0;
    const float inv1 = 1.f / l1;

    const int row0 = b * NN + qt * 64 + w * 16 + r;
    #pragma unroll
    for (int nf = 0; nf < 8; nf++) {
        const int col = h * DD + nf * 8 + 2 * q;
        *(__half2*)&out[(size_t)row0 * CC + col] =
            __floats2half2_rn(o[nf][0] * inv0, o[nf][1] * inv0);
        *(__half2*)&out[(size_t)(row0 + 8) * CC + col] =
            __floats2half2_rn(o[nf][2] * inv1, o[nf][3] * inv1);
    }
}

// ---------------------------------------------------------------------------
// Launch
// ---------------------------------------------------------------------------
extern "C" void kernel_launch(void* const* d_in, const int* in_sizes, int n_in,
                              void* d_out, int out_size)
{
    const float* x      = (const float*)d_in[0];
    const float* amask  = (const float*)d_in[1];
    const float* W_qkv  = (const float*)d_in[2];
    const float* b_qkv  = (const float*)d_in[3];
    const float* W_proj = (const float*)d_in[4];
    const float* b_proj = (const float*)d_in[5];
    float* out = (float*)d_out;

    __half *x_h, *wqkv_t, *wproj_t, *qkv_h, *att_h;
    cudaGetSymbolAddress((void**)&x_h,     g_x_h);
    cudaGetSymbolAddress((void**)&wqkv_t,  g_wqkv_t);
    cudaGetSymbolAddress((void**)&wproj_t, g_wproj_t);
    cudaGetSymbolAddress((void**)&qkv_h,   g_qkv_h);
    cudaGetSymbolAddress((void**)&att_h,   g_att_h);

    // 0) conversions
    {
        const int n4 = M_ROWS * CC / 4;
        cvt_f32_f16_kernel<<<(n4 + 255) / 256, 256>>>(x, x_h, n4);
        transpose_cvt_kernel<<<dim3(QKV_COLS / 32, CC / 32), dim3(32, 8)>>>(
            W_qkv, wqkv_t, CC, QKV_COLS);
        transpose_cvt_kernel<<<dim3(CC / 32, CC / 32), dim3(32, 8)>>>(
            W_proj, wproj_t, CC, CC);
    }
    // 1) QKV projection (fp16 out)
    {
        dim3 grid(QKV_COLS / 128, M_ROWS / 128);
        gemm_f16_kernel<__half><<<grid, 256>>>(x_h, wqkv_t, b_qkv, qkv_h,
                                               M_ROWS, CC, QKV_COLS);
    }
    // 2) Attention (fp16 out)
    {
        dim3 grid(BB * HH, NN / 64);
        attn_f16_kernel<<<grid, 128>>>(qkv_h, amask, att_h);
    }
    // 3) Output projection (fp32 out)
    {
        dim3 grid(CC / 128, M_ROWS / 128);
        gemm_f16_kernel<float><<<grid, 256>>>(att_h, wproj_t, b_proj, out,
                                              M_ROWS, CC, CC);
    }
}

// round 5
// speedup vs baseline: 8.3925x; 1.0161x over previous
#include <cuda_runtime.h>
#include <cuda_fp16.h>
#include <cstdint>

#define BB 8
#define NN 1024
#define CC 768
#define HH 12
#define DD 64
#define M_ROWS (BB * NN)        // 8192
#define QKV_COLS (3 * CC)       // 2304
#define ATT_SCALE 0.125f
#define LOG2E 1.4426950408889634f

// Scratch (device globals: allocation-free)
__device__ __half g_x_h[(size_t)M_ROWS * CC];
__device__ __half g_wqkv_t[(size_t)QKV_COLS * CC];   // [2304][768] K-major
__device__ __half g_wproj_t[(size_t)CC * CC];        // [768][768]  K-major
__device__ __half g_qkv_h[(size_t)M_ROWS * QKV_COLS];
__device__ __half g_att_h[(size_t)M_ROWS * CC];

// ---------------------------------------------------------------------------
// PTX helpers
// ---------------------------------------------------------------------------
__device__ __forceinline__ unsigned sptr(const void* p) {
    return (unsigned)__cvta_generic_to_shared(p);
}
__device__ __forceinline__ void cp16(unsigned s, const void* g) {
    asm volatile("cp.async.cg.shared.global [%0], [%1], 16;\n" :: "r"(s), "l"(g));
}
__device__ __forceinline__ void cp_commit() {
    asm volatile("cp.async.commit_group;\n");
}
template <int N>
__device__ __forceinline__ void cp_wait() {
    asm volatile("cp.async.wait_group %0;\n" :: "n"(N));
}
__device__ __forceinline__ void ldsm4(unsigned r[4], unsigned a) {
    asm volatile("ldmatrix.sync.aligned.m8n8.x4.shared.b16 {%0,%1,%2,%3}, [%4];\n"
                 : "=r"(r[0]), "=r"(r[1]), "=r"(r[2]), "=r"(r[3]) : "r"(a));
}
__device__ __forceinline__ void ldsm4t(unsigned r[4], unsigned a) {
    asm volatile("ldmatrix.sync.aligned.m8n8.x4.trans.shared.b16 {%0,%1,%2,%3}, [%4];\n"
                 : "=r"(r[0]), "=r"(r[1]), "=r"(r[2]), "=r"(r[3]) : "r"(a));
}
__device__ __forceinline__ void mma16816(float c[4], const unsigned a[4],
                                         unsigned b0, unsigned b1) {
    asm volatile(
        "mma.sync.aligned.m16n8k16.row.col.f32.f16.f16.f32 "
        "{%0,%1,%2,%3},{%4,%5,%6,%7},{%8,%9},{%0,%1,%2,%3};\n"
        : "+f"(c[0]), "+f"(c[1]), "+f"(c[2]), "+f"(c[3])
        : "r"(a[0]), "r"(a[1]), "r"(a[2]), "r"(a[3]), "r"(b0), "r"(b1));
}
__device__ __forceinline__ unsigned f2h2(float lo, float hi) {
    __half2 h = __floats2half2_rn(lo, hi);
    return *(unsigned*)&h;
}
__device__ __forceinline__ float ex2(float x) {
    float r;
    asm("ex2.approx.f32 %0, %1;" : "=f"(r) : "f"(x));
    return r;
}
__device__ __forceinline__ void store2(__half* p, float x, float y) {
    *(__half2*)p = __floats2half2_rn(x, y);
}
__device__ __forceinline__ void store2(float* p, float x, float y) {
    *(float2*)p = make_float2(x, y);
}

// ---------------------------------------------------------------------------
// conversions
// ---------------------------------------------------------------------------
__global__ void cvt_f32_f16_kernel(const float* __restrict__ in,
                                   __half* __restrict__ out, int n4) {
    int i = blockIdx.x * 256 + threadIdx.x;
    if (i < n4) {
        float4 v = ((const float4*)in)[i];
        __half2 h0 = __floats2half2_rn(v.x, v.y);
        __half2 h1 = __floats2half2_rn(v.z, v.w);
        ((uint2*)out)[i] = make_uint2(*(unsigned*)&h0, *(unsigned*)&h1);
    }
}

__global__ void transpose_cvt_kernel(const float* __restrict__ W,
                                     __half* __restrict__ Wt,
                                     int rows, int cols) {
    __shared__ float t[32][33];
    const int x  = blockIdx.x * 32 + threadIdx.x;
    const int y0 = blockIdx.y * 32 + threadIdx.y;
    #pragma unroll
    for (int i = 0; i < 4; i++)
        t[threadIdx.y + i * 8][threadIdx.x] = W[(size_t)(y0 + i * 8) * cols + x];
    __syncthreads();
    const int xo  = blockIdx.y * 32 + threadIdx.x;
    const int yo0 = blockIdx.x * 32 + threadIdx.y;
    #pragma unroll
    for (int i = 0; i < 4; i++)
        Wt[(size_t)(yo0 + i * 8) * rows + xo] =
            __float2half(t[threadIdx.x][threadIdx.y + i * 8]);
}

// ---------------------------------------------------------------------------
// HMMA GEMM: C[M,N] = A[M,K] @ Bt[N,K]^T + bias.
// CTA tile (MB*64) x 128, BK=32, 3-stage cp.async pipeline, 256 threads,
// 8 warps (4m x 2n), warp tile (MB*16) x 64.
// smem rows = 64B (32 halves) = 4 chunks; swizzle c ^= (row>>1)&3.
// ---------------------------------------------------------------------------
template <int MB, typename OutT>
__global__ __launch_bounds__(256) void gemm_mma_kernel(
    const __half* __restrict__ A, const __half* __restrict__ Bt,
    const float* __restrict__ bias, OutT* __restrict__ C,
    int M, int Kdim, int Ncols)
{
    constexpr int ASZ   = MB * 64 * 64;          // bytes per A stage
    constexpr int BSZ   = 128 * 64;              // bytes per B stage
    constexpr int STAGE = ASZ + BSZ;
    constexpr int ACH   = MB * 256;              // A chunks per stage
    constexpr int TC    = ACH + 512;             // total chunks
    constexpr int PER   = TC / 256;

    extern __shared__ char smem[];
    const uint32_t sb = sptr(smem);

    const int tid  = threadIdx.x;
    const int lane = tid & 31;
    const int wid  = tid >> 5;
    const int wm   = wid >> 1;                  // 0..3
    const int wn   = wid & 1;                   // 0..1
    const int r    = lane >> 2;
    const int q    = lane & 3;
    const int mat  = lane >> 3;
    const int mi   = lane & 7;

    const int rowBase = blockIdx.y * (MB * 64);
    const int colBase = blockIdx.x * 128;

    float acc[MB][8][4];
    #pragma unroll
    for (int mb = 0; mb < MB; mb++)
        #pragma unroll
        for (int nf = 0; nf < 8; nf++)
            #pragma unroll
            for (int c = 0; c < 4; c++) acc[mb][nf][c] = 0.f;

    const int nt = Kdim >> 5;

    auto stage = [&](int buf, int k0) {
        const uint32_t base = sb + buf * STAGE;
        #pragma unroll
        for (int i = 0; i < PER; i++) {
            const int j = i * 256 + tid;
            if (j < ACH) {
                const int row = j >> 2, c = j & 3;
                cp16(base + row * 64 + ((c ^ ((row >> 1) & 3)) * 16),
                     A + (size_t)(rowBase + row) * Kdim + k0 + c * 8);
            } else {
                const int jj = j - ACH;
                const int row = jj >> 2, c = jj & 3;
                cp16(base + ASZ + row * 64 + ((c ^ ((row >> 1) & 3)) * 16),
                     Bt + (size_t)(colBase + row) * Kdim + k0 + c * 8);
            }
        }
        cp_commit();
    };

    stage(0, 0);
    stage(1, 32);

    int buf = 0;
    for (int it = 0; it < nt; it++) {
        if (it + 2 < nt) cp_wait<1>(); else cp_wait<0>();
        __syncthreads();
        if (it + 2 < nt) {
            int nb = buf + 2; if (nb >= 3) nb -= 3;
            stage(nb, (it + 2) * 32);
        }

        const uint32_t bA = sb + buf * STAGE;
        const uint32_t bB = bA + ASZ;

        #pragma unroll
        for (int ks = 0; ks < 2; ks++) {
            const int chb = 2 * ks + (mat >> 1);
            unsigned af[MB][4];
            #pragma unroll
            for (int mb = 0; mb < MB; mb++) {
                const int rowA = wm * (MB * 16) + mb * 16 + (mat & 1) * 8 + mi;
                ldsm4(af[mb], bA + rowA * 64 + ((chb ^ ((rowA >> 1) & 3)) * 16));
            }
            unsigned bf[4][4];
            #pragma unroll
            for (int np = 0; np < 4; np++) {
                const int rowB = wn * 64 + np * 16 + (mat & 1) * 8 + mi;
                ldsm4(bf[np], bB + rowB * 64 + ((chb ^ ((rowB >> 1) & 3)) * 16));
            }
            #pragma unroll
            for (int mb = 0; mb < MB; mb++)
                #pragma unroll
                for (int nf = 0; nf < 8; nf++)
                    mma16816(acc[mb][nf], af[mb],
                             bf[nf >> 1][nf & 1], bf[nf >> 1][(nf & 1) + 2]);
        }
        if (++buf == 3) buf = 0;
    }

    #pragma unroll
    for (int mb = 0; mb < MB; mb++) {
        const int row0 = rowBase + wm * (MB * 16) + mb * 16 + r;
        #pragma unroll
        for (int nf = 0; nf < 8; nf++) {
            const int col = colBase + wn * 64 + nf * 8 + 2 * q;
            const float2 bv = *(const float2*)&bias[col];
            store2(&C[(size_t)row0 * Ncols + col],
                   acc[mb][nf][0] + bv.x, acc[mb][nf][1] + bv.y);
            store2(&C[(size_t)(row0 + 8) * Ncols + col],
                   acc[mb][nf][2] + bv.x, acc[mb][nf][3] + bv.y);
        }
    }
}

#define GEMM_SMEM_MB4 (3 * (4 * 64 * 64 + 128 * 64))   // 73728
#define GEMM_SMEM_MB2 (3 * (2 * 64 * 64 + 128 * 64))   // 49152

// ---------------------------------------------------------------------------
// fp16 flash attention. CTA = (b,h, 128 q-rows), 8 warps x 16 rows, 256 thr.
// Skips fully-padded key tiles (exact: exp underflows to 0 in reference).
// Softmax in exp2 domain. K tiles of 64 keys, cp.async double-buffered.
// smem layout (bytes): Q[0,16384), KV[16384,49152), Mask[49152,53248), P int.
// ---------------------------------------------------------------------------
#define AT_Q  0
#define AT_KV 16384
#define AT_M  49152
#define AT_P  53248
#define AT_SMEM (AT_P + 16)

__global__ __launch_bounds__(256) void attn_f16_kernel(
    const __half* __restrict__ qkv, const float* __restrict__ mask,
    __half* __restrict__ out)
{
    extern __shared__ char smem[];
    const uint32_t sb  = sptr(smem);
    const uint32_t sQ  = sb + AT_Q;
    const uint32_t sKV = sb + AT_KV;
    float* Ms = (float*)(smem + AT_M);
    int* sP   = (int*)(smem + AT_P);

    const int bh = blockIdx.x;
    const int b  = bh / HH;
    const int h  = bh % HH;
    const int qt = blockIdx.y;

    const int tid  = threadIdx.x;
    const int lane = tid & 31;
    const int w    = tid >> 5;
    const int r    = lane >> 2;
    const int q    = lane & 3;
    const int mat  = lane >> 3;
    const int mi   = lane & 7;

    if (tid == 0) *sP = NN;

    // stage Q: 128 rows x 8 chunks
    #pragma unroll
    for (int i = 0; i < 4; i++) {
        const int j = tid + i * 256;
        const int row = j >> 3, c0 = j & 7;
        cp16(sQ + (row * 8 + (c0 ^ (row & 7))) * 16,
             qkv + (size_t)(b * NN + qt * 128 + row) * QKV_COLS + h * DD + c0 * 8);
    }
    cp_commit();

    auto stageKV = [&](int buf, int kt) {
        #pragma unroll
        for (int i = 0; i < 4; i++) {
            const int j  = tid + i * 256;
            const int kv = j >> 9;
            const int jj = j & 511;
            const int row = jj >> 3, c0 = jj & 7;
            cp16(sKV + (buf * 1024 + kv * 512 + row * 8 + (c0 ^ (row & 7))) * 16,
                 qkv + (size_t)(b * NN + kt * 64 + row) * QKV_COLS +
                     (kv + 1) * CC + h * DD + c0 * 8);
        }
        cp_commit();
    };

    stageKV(0, 0);

    // stage mask (pre-multiplied by log2e)
    {
        float4 mv = ((const float4*)(mask + b * NN))[tid];
        mv.x *= LOG2E; mv.y *= LOG2E; mv.z *= LOG2E; mv.w *= LOG2E;
        ((float4*)Ms)[tid] = mv;
    }

    cp_wait<0>();
    __syncthreads();

    // first padded position -> number of key tiles to process
    {
        int firstPad = NN;
        #pragma unroll
        for (int i = 0; i < 4; i++) {
            const int idx = tid * 4 + i;
            if (Ms[idx] < -1e8f) { firstPad = idx; break; }
        }
        if (firstPad < NN) atomicMin(sP, firstPad);
    }
    __syncthreads();
    const int ntk = (*sP + 63) >> 6;

    // Q fragments, persistent
    unsigned qf[4][4];
    #pragma unroll
    for (int ks = 0; ks < 4; ks++) {
        const int rowQ = w * 16 + (mat & 1) * 8 + mi;
        const int ch   = 2 * ks + (mat >> 1);
        ldsm4(qf[ks], sQ + (rowQ * 8 + (ch ^ (rowQ & 7))) * 16);
    }

    float o[8][4];
    #pragma unroll
    for (int nf = 0; nf < 8; nf++)
        #pragma unroll
        for (int c = 0; c < 4; c++) o[nf][c] = 0.f;
    float m0 = -1e30f, m1 = -1e30f, l0 = 0.f, l1 = 0.f;

    const float SC2 = ATT_SCALE * LOG2E;

    for (int kt = 0; kt < ntk; kt++) {
        if (kt + 1 < ntk) { stageKV((kt + 1) & 1, kt + 1); cp_wait<1>(); }
        else              { cp_wait<0>(); }
        __syncthreads();

        const uint32_t sK = sKV + (kt & 1) * 1024 * 16;
        const uint32_t sV = sK + 512 * 16;

        // ---- S = Q K^T ----
        float s[8][4];
        #pragma unroll
        for (int nf = 0; nf < 8; nf++)
            #pragma unroll
            for (int c = 0; c < 4; c++) s[nf][c] = 0.f;

        #pragma unroll
        for (int ks = 0; ks < 4; ks++) {
            unsigned bk[4][4];
            #pragma unroll
            for (int np = 0; np < 4; np++) {
                const int rowK = np * 16 + (mat & 1) * 8 + mi;
                const int ch   = 2 * ks + (mat >> 1);
                ldsm4(bk[np], sK + (rowK * 8 + (ch ^ (rowK & 7))) * 16);
            }
            #pragma unroll
            for (int nf = 0; nf < 8; nf++)
                mma16816(s[nf], qf[ks],
                         bk[nf >> 1][nf & 1], bk[nf >> 1][(nf & 1) + 2]);
        }

        // ---- scale + mask (exp2 domain) + online softmax ----
        float tmax0 = -1e30f, tmax1 = -1e30f;
        #pragma unroll
        for (int nf = 0; nf < 8; nf++) {
            const int col = kt * 64 + nf * 8 + 2 * q;
            const float2 mv = *(const float2*)&Ms[col];
            s[nf][0] = s[nf][0] * SC2 + mv.x;
            s[nf][1] = s[nf][1] * SC2 + mv.y;
            s[nf][2] = s[nf][2] * SC2 + mv.x;
            s[nf][3] = s[nf][3] * SC2 + mv.y;
            tmax0 = fmaxf(tmax0, fmaxf(s[nf][0], s[nf][1]));
            tmax1 = fmaxf(tmax1, fmaxf(s[nf][2], s[nf][3]));
        }
        #pragma unroll
        for (int off = 1; off <= 2; off <<= 1) {
            tmax0 = fmaxf(tmax0, __shfl_xor_sync(0xffffffffu, tmax0, off));
            tmax1 = fmaxf(tmax1, __shfl_xor_sync(0xffffffffu, tmax1, off));
        }
        const float nm0 = fmaxf(m0, tmax0);
        const float nm1 = fmaxf(m1, tmax1);
        const float cr0 = ex2(m0 - nm0);
        const float cr1 = ex2(m1 - nm1);
        l0 *= cr0; l1 *= cr1;
        #pragma unroll
        for (int nf = 0; nf < 8; nf++) {
            o[nf][0] *= cr0; o[nf][1] *= cr0;
            o[nf][2] *= cr1; o[nf][3] *= cr1;
        }
        m0 = nm0; m1 = nm1;

        #pragma unroll
        for (int nf = 0; nf < 8; nf++) {
            s[nf][0] = ex2(s[nf][0] - nm0);
            s[nf][1] = ex2(s[nf][1] - nm0);
            s[nf][2] = ex2(s[nf][2] - nm1);
            s[nf][3] = ex2(s[nf][3] - nm1);
            l0 += s[nf][0] + s[nf][1];
            l1 += s[nf][2] + s[nf][3];
        }

        // ---- P fragments in registers ----
        unsigned ap[4][4];
        #pragma unroll
        for (int ks = 0; ks < 4; ks++) {
            ap[ks][0] = f2h2(s[2 * ks][0],     s[2 * ks][1]);
            ap[ks][1] = f2h2(s[2 * ks][2],     s[2 * ks][3]);
            ap[ks][2] = f2h2(s[2 * ks + 1][0], s[2 * ks + 1][1]);
            ap[ks][3] = f2h2(s[2 * ks + 1][2], s[2 * ks + 1][3]);
        }

        // ---- O += P V ----
        #pragma unroll
        for (int ks = 0; ks < 4; ks++) {
            unsigned bv[4][4];
            #pragma unroll
            for (int np = 0; np < 4; np++) {
                const int rowV = ks * 16 + (mat & 1) * 8 + mi;
                const int ch   = 2 * np + (mat >> 1);
                ldsm4t(bv[np], sV + (rowV * 8 + (ch ^ (rowV & 7))) * 16);
            }
            #pragma unroll
            for (int nf = 0; nf < 8; nf++)
                mma16816(o[nf], ap[ks],
                         bv[nf >> 1][(nf & 1) * 2], bv[nf >> 1][(nf & 1) * 2 + 1]);
        }
        __syncthreads();
    }

    // ---- finalize ----
    #pragma unroll
    for (int off = 1; off <= 2; off <<= 1) {
        l0 += __shfl_xor_sync(0xffffffffu, l0, off);
        l1 += __shfl_xor_sync(0xffffffffu, l1, off);
    }
    const float inv0 = 1.f / l0;
    const float inv1 = 1.f / l1;

    const int row0 = b * NN + qt * 128 + w * 16 + r;
    #pragma unroll
    for (int nf = 0; nf < 8; nf++) {
        const int col = h * DD + nf * 8 + 2 * q;
        *(__half2*)&out[(size_t)row0 * CC + col] =
            __floats2half2_rn(o[nf][0] * inv0, o[nf][1] * inv0);
        *(__half2*)&out[(size_t)(row0 + 8) * CC + col] =
            __floats2half2_rn(o[nf][2] * inv1, o[nf][3] * inv1);
    }
}

// ---------------------------------------------------------------------------
// Launch
// ---------------------------------------------------------------------------
extern "C" void kernel_launch(void* const* d_in, const int* in_sizes, int n_in,
                              void* d_out, int out_size)
{
    const float* x      = (const float*)d_in[0];
    const float* amask  = (const float*)d_in[1];
    const float* W_qkv  = (const float*)d_in[2];
    const float* b_qkv  = (const float*)d_in[3];
    const float* W_proj = (const float*)d_in[4];
    const float* b_proj = (const float*)d_in[5];
    float* out = (float*)d_out;

    __half *x_h, *wqkv_t, *wproj_t, *qkv_h, *att_h;
    cudaGetSymbolAddress((void**)&x_h,     g_x_h);
    cudaGetSymbolAddress((void**)&wqkv_t,  g_wqkv_t);
    cudaGetSymbolAddress((void**)&wproj_t, g_wproj_t);
    cudaGetSymbolAddress((void**)&qkv_h,   g_qkv_h);
    cudaGetSymbolAddress((void**)&att_h,   g_att_h);

    static bool attr_set = false;
    if (!attr_set) {
        cudaFuncSetAttribute(gemm_mma_kernel<4, __half>,
                             cudaFuncAttributeMaxDynamicSharedMemorySize, GEMM_SMEM_MB4);
        cudaFuncSetAttribute(gemm_mma_kernel<2, float>,
                             cudaFuncAttributeMaxDynamicSharedMemorySize, GEMM_SMEM_MB2);
        cudaFuncSetAttribute(attn_f16_kernel,
                             cudaFuncAttributeMaxDynamicSharedMemorySize, AT_SMEM);
        attr_set = true;
    }

    // 0) conversions
    {
        const int n4 = M_ROWS * CC / 4;
        cvt_f32_f16_kernel<<<(n4 + 255) / 256, 256>>>(x, x_h, n4);
        transpose_cvt_kernel<<<dim3(QKV_COLS / 32, CC / 32), dim3(32, 8)>>>(
            W_qkv, wqkv_t, CC, QKV_COLS);
        transpose_cvt_kernel<<<dim3(CC / 32, CC / 32), dim3(32, 8)>>>(
            W_proj, wproj_t, CC, CC);
    }
    // 1) QKV projection (fp16 out), 256x128 tiles
    {
        dim3 grid(QKV_COLS / 128, M_ROWS / 256);
        gemm_mma_kernel<4, __half><<<grid, 256, GEMM_SMEM_MB4>>>(
            x_h, wqkv_t, b_qkv, qkv_h, M_ROWS, CC, QKV_COLS);
    }
    // 2) Attention (fp16 out)
    {
        dim3 grid(BB * HH, NN / 128);
        attn_f16_kernel<<<grid, 256, AT_SMEM>>>(qkv_h, amask, att_h);
    }
    // 3) Output projection (fp32 out), 128x128 tiles
    {
        dim3 grid(CC / 128, M_ROWS / 128);
        gemm_mma_kernel<2, float><<<grid, 256, GEMM_SMEM_MB2>>>(
            att_h, wproj_t, b_proj, out, M_ROWS, CC, CC);
    }
}